// round 8
// baseline (speedup 1.0000x reference)
#include <cuda_runtime.h>
#include <cuda_bf16.h>
#include <cstdint>

// ---------------------------------------------------------------------------
// GNN: 2-layer GraphSAGE (mean aggr) + global mean pool.
// GEMMs: mma.sync m16n8k16 bf16 (HMMA), split-bf16 3-term (AhBh+AhBl+AlBh).
// hi/lo planes stored as SEPARATE bf16x2 (uint32) arrays -> ldmatrix feeds
// MMA directly, no PRMT in the inner loop. SW64 smem swizzle, cp.async 2-stage.
// Launch count minimized via zero-invariants (device globals start zeroed;
// k_fill re-zeroes g_cnt, k_final re-zeroes g_gsum/g_gcnt each run).
// ---------------------------------------------------------------------------

#define MAXN 100000
#define MAXE 600000
#define NG   64
#define DD   128

// hi/lo bf16x2 planes (each uint32 = 2 consecutive-k bf16, low half = even k)
__device__ uint32_t g_xh [MAXN * 64], g_xl [MAXN * 64];
__device__ uint32_t g_ah [MAXN * 64], g_al [MAXN * 64];
__device__ uint32_t g_h1h[MAXN * 64], g_h1l[MAXN * 64];
__device__ float    g_h2 [MAXN * DD];
__device__ uint32_t g_w1h[128 * 128], g_w1l[128 * 128];   // [n][k/2], K=256 stacked
__device__ uint32_t g_w2h[128 * 128], g_w2l[128 * 128];
__device__ int      g_cnt[MAXN];        // invariant: all-zero at kernel_launch entry
__device__ int      g_rowptr[MAXN + 1];
__device__ int      g_cursor[MAXN];
__device__ int      g_col[MAXE];
__device__ float    g_gsum[NG * DD];    // invariant: all-zero at entry
__device__ float    g_gcnt[NG];         // invariant: all-zero at entry

// ------------------------------------------------------------- bf16 helpers
__device__ __forceinline__ uint2 split2(float a, float b) {
    __nv_bfloat16 ah = __float2bfloat16(a), bh = __float2bfloat16(b);
    float ar = a - __bfloat162float(ah);
    float br = b - __bfloat162float(bh);
    __nv_bfloat16 al = __float2bfloat16(ar), bl = __float2bfloat16(br);
    uint2 r;
    r.x = (uint32_t)__bfloat16_as_ushort(ah) |
          ((uint32_t)__bfloat16_as_ushort(bh) << 16);
    r.y = (uint32_t)__bfloat16_as_ushort(al) |
          ((uint32_t)__bfloat16_as_ushort(bl) << 16);
    return r;
}
// reconstruct 2 floats from hi-plane word + lo-plane word
__device__ __forceinline__ float2 join2(uint32_t h, uint32_t l) {
    float2 r;
    r.x = __uint_as_float(h << 16) + __uint_as_float(l << 16);
    r.y = __uint_as_float(h & 0xffff0000u) + __uint_as_float(l & 0xffff0000u);
    return r;
}

// --------------------------------------------------------------- PTX helpers
__device__ __forceinline__ uint32_t smem_u32(const void* p) {
    uint32_t a;
    asm("{ .reg .u64 t; cvta.to.shared.u64 t, %1; cvt.u32.u64 %0, t; }"
        : "=r"(a) : "l"(p));
    return a;
}
__device__ __forceinline__ void cpasync16(uint32_t smem, const void* gmem, int sz) {
    asm volatile("cp.async.ca.shared.global [%0], [%1], 16, %2;"
                 :: "r"(smem), "l"(gmem), "r"(sz));
}
__device__ __forceinline__ void cp_commit() { asm volatile("cp.async.commit_group;"); }
__device__ __forceinline__ void cp_wait1()  { asm volatile("cp.async.wait_group 1;"); }
__device__ __forceinline__ void cp_wait0()  { asm volatile("cp.async.wait_group 0;"); }

__device__ __forceinline__ void ldmx4(uint32_t (&r)[4], uint32_t addr) {
    asm volatile("ldmatrix.sync.aligned.m8n8.x4.shared.b16 {%0,%1,%2,%3}, [%4];"
        : "=r"(r[0]), "=r"(r[1]), "=r"(r[2]), "=r"(r[3]) : "r"(addr));
}
__device__ __forceinline__ void mma_bf16(float (&c)[4],
                                         const uint32_t (&a)[4],
                                         uint32_t b0, uint32_t b1) {
    asm volatile(
        "mma.sync.aligned.m16n8k16.row.col.f32.bf16.bf16.f32 "
        "{%0,%1,%2,%3}, {%4,%5,%6,%7}, {%8,%9}, {%0,%1,%2,%3};"
        : "+f"(c[0]), "+f"(c[1]), "+f"(c[2]), "+f"(c[3])
        : "r"(a[0]), "r"(a[1]), "r"(a[2]), "r"(a[3]), "r"(b0), "r"(b1));
}

#define SW64(o) ((o) ^ (((o) >> 3) & 0x30))

// ------------------------------------------------------------- degree counts
__global__ void k_count(const int* __restrict__ dst, int e) {
    int i = blockIdx.x * blockDim.x + threadIdx.x;
    if (i < e) atomicAdd(&g_cnt[dst[i]], 1);
}

// ------------------------------------- single-block exclusive scan -> rowptr
__global__ void k_scan_all(int n, int e) {
    __shared__ int s[1024];
    int t = threadIdx.x;
    int CH = (n + 1023) >> 10;
    int b0 = t * CH; if (b0 > n) b0 = n;
    int b1 = b0 + CH; if (b1 > n) b1 = n;
    int sum = 0;
    for (int i = b0; i < b1; i++) sum += g_cnt[i];
    s[t] = sum;
    __syncthreads();
    #pragma unroll
    for (int off = 1; off < 1024; off <<= 1) {
        int u = (t >= off) ? s[t - off] : 0;
        __syncthreads();
        s[t] += u;
        __syncthreads();
    }
    int run = s[t] - sum;   // exclusive prefix at b0
    for (int i = b0; i < b1; i++) {
        int c = g_cnt[i];
        g_rowptr[i] = run;
        g_cursor[i] = run;
        run += c;
    }
    if (t == 0) g_rowptr[n] = e;
}

// ------------------------- CSR bucket fill (+ restore g_cnt zero-invariant)
__global__ void k_fill(const int* __restrict__ src, const int* __restrict__ dst,
                       int e, int n) {
    int i = blockIdx.x * blockDim.x + threadIdx.x;
    if (i < e) {
        int d = dst[i];
        int p = atomicAdd(&g_cursor[d], 1);
        g_col[p] = src[i];
    }
    if (i < n) g_cnt[i] = 0;
}

// ---------------------- one-time conversions: x -> hi/lo, weights -> hi/lo
__global__ void k_cvtall(const float2* __restrict__ x2,
                         const float* __restrict__ W1l, const float* __restrict__ W1r,
                         const float* __restrict__ W2l, const float* __restrict__ W2r,
                         int n) {
    int i = blockIdx.x * blockDim.x + threadIdx.x;
    int nx = n * 64;
    if (i < nx) {
        float2 v = x2[i];
        uint2 p = split2(v.x, v.y);
        g_xh[i] = p.x;
        g_xl[i] = p.y;
    } else {
        int j = i - nx;
        if (j >= 2 * 128 * 128) return;
        int layer = j >> 14;
        int idx = j & 16383;
        int nn = idx >> 7;         // output col 0..127
        int kp = idx & 127;        // k-pair 0..127 (stacked K=256)
        int k = kp * 2;
        float a, b;
        if (layer == 0) {
            if (k < 128) { a = W1l[k * 128 + nn]; b = W1l[(k + 1) * 128 + nn]; }
            else         { a = W1r[(k - 128) * 128 + nn]; b = W1r[(k - 127) * 128 + nn]; }
        } else {
            if (k < 128) { a = W2l[k * 128 + nn]; b = W2l[(k + 1) * 128 + nn]; }
            else         { a = W2r[(k - 128) * 128 + nn]; b = W2r[(k - 127) * 128 + nn]; }
        }
        uint2 p = split2(a, b);
        if (layer == 0) { g_w1h[nn * 128 + kp] = p.x; g_w1l[nn * 128 + kp] = p.y; }
        else            { g_w2h[nn * 128 + kp] = p.x; g_w2l[nn * 128 + kp] = p.y; }
    }
}

// -------------------------------- mean aggregation, fp32 input (layer 1)
__global__ void k_agg_f(const float4* __restrict__ xin, int n) {
    int gt = blockIdx.x * blockDim.x + threadIdx.x;
    int node = gt >> 5;
    int lane = gt & 31;
    if (node >= n) return;
    int beg = g_rowptr[node];
    int end = g_rowptr[node + 1];
    float4 a0 = {0, 0, 0, 0}, a1 = {0, 0, 0, 0}, a2 = {0, 0, 0, 0}, a3 = {0, 0, 0, 0};
    int e = beg;
    for (; e + 3 < end; e += 4) {
        int j0 = g_col[e], j1 = g_col[e + 1], j2 = g_col[e + 2], j3 = g_col[e + 3];
        float4 v0 = __ldg(&xin[j0 * 32 + lane]);
        float4 v1 = __ldg(&xin[j1 * 32 + lane]);
        float4 v2 = __ldg(&xin[j2 * 32 + lane]);
        float4 v3 = __ldg(&xin[j3 * 32 + lane]);
        a0.x += v0.x; a0.y += v0.y; a0.z += v0.z; a0.w += v0.w;
        a1.x += v1.x; a1.y += v1.y; a1.z += v1.z; a1.w += v1.w;
        a2.x += v2.x; a2.y += v2.y; a2.z += v2.z; a2.w += v2.w;
        a3.x += v3.x; a3.y += v3.y; a3.z += v3.z; a3.w += v3.w;
    }
    for (; e < end; e++) {
        int j = g_col[e];
        float4 v = __ldg(&xin[j * 32 + lane]);
        a0.x += v.x; a0.y += v.y; a0.z += v.z; a0.w += v.w;
    }
    float4 acc;
    acc.x = (a0.x + a1.x) + (a2.x + a3.x);
    acc.y = (a0.y + a1.y) + (a2.y + a3.y);
    acc.z = (a0.z + a1.z) + (a2.z + a3.z);
    acc.w = (a0.w + a1.w) + (a2.w + a3.w);
    int deg = end - beg;
    float s = 1.0f / (float)(deg > 0 ? deg : 1);
    uint2 p0 = split2(acc.x * s, acc.y * s);
    uint2 p1 = split2(acc.z * s, acc.w * s);
    uint2 h = make_uint2(p0.x, p1.x);
    uint2 l = make_uint2(p0.y, p1.y);
    *(uint2*)&g_ah[node * 64 + 2 * lane] = h;
    *(uint2*)&g_al[node * 64 + 2 * lane] = l;
}

// -------------------------------- mean aggregation, hi/lo input (layer 2)
__global__ void k_agg_p(int n) {
    int gt = blockIdx.x * blockDim.x + threadIdx.x;
    int node = gt >> 5;
    int lane = gt & 31;
    if (node >= n) return;
    int beg = g_rowptr[node];
    int end = g_rowptr[node + 1];
    float4 a0 = {0, 0, 0, 0}, a1 = {0, 0, 0, 0};
    int e = beg;
    for (; e + 1 < end; e += 2) {
        int j0 = g_col[e], j1 = g_col[e + 1];
        uint2 h0 = __ldg((const uint2*)&g_h1h[j0 * 64 + 2 * lane]);
        uint2 l0 = __ldg((const uint2*)&g_h1l[j0 * 64 + 2 * lane]);
        uint2 h1 = __ldg((const uint2*)&g_h1h[j1 * 64 + 2 * lane]);
        uint2 l1 = __ldg((const uint2*)&g_h1l[j1 * 64 + 2 * lane]);
        float2 f00 = join2(h0.x, l0.x), f01 = join2(h0.y, l0.y);
        float2 f10 = join2(h1.x, l1.x), f11 = join2(h1.y, l1.y);
        a0.x += f00.x; a0.y += f00.y; a0.z += f01.x; a0.w += f01.y;
        a1.x += f10.x; a1.y += f10.y; a1.z += f11.x; a1.w += f11.y;
    }
    for (; e < end; e++) {
        int j = g_col[e];
        uint2 h = __ldg((const uint2*)&g_h1h[j * 64 + 2 * lane]);
        uint2 l = __ldg((const uint2*)&g_h1l[j * 64 + 2 * lane]);
        float2 f0 = join2(h.x, l.x), f1 = join2(h.y, l.y);
        a0.x += f0.x; a0.y += f0.y; a0.z += f1.x; a0.w += f1.y;
    }
    float4 acc;
    acc.x = a0.x + a1.x; acc.y = a0.y + a1.y;
    acc.z = a0.z + a1.z; acc.w = a0.w + a1.w;
    int deg = end - beg;
    float s = 1.0f / (float)(deg > 0 ? deg : 1);
    uint2 p0 = split2(acc.x * s, acc.y * s);
    uint2 p1 = split2(acc.z * s, acc.w * s);
    *(uint2*)&g_ah[node * 64 + 2 * lane] = make_uint2(p0.x, p1.x);
    *(uint2*)&g_al[node * 64 + 2 * lane] = make_uint2(p0.y, p1.y);
}

// ---------------------- split-bf16 HMMA dual GEMM via ldmatrix (no PRMTs)
// C[128/blk, 128] = [A0 | A1](K=256) @ Bw^T + bias; 3 terms AhBh+AhBl+AlBh.
// smem per stage: Ah(8K) Al(8K) Bh(8K) Bl(8K), SW64 swizzle, 2 stages.
#define STAGE 32768

template <bool RELU, bool PAIR_OUT>
__global__ void __launch_bounds__(256, 2)
k_gemm(const uint32_t* __restrict__ A0h, const uint32_t* __restrict__ A0l,
       const uint32_t* __restrict__ A1h, const uint32_t* __restrict__ A1l,
       const uint32_t* __restrict__ Bh,  const uint32_t* __restrict__ Bl,
       const float* __restrict__ bias,
       uint32_t* __restrict__ Coh, uint32_t* __restrict__ Col,
       float* __restrict__ Cof, int n) {
    extern __shared__ __align__(16) unsigned char smraw[];
    uint32_t sbase = smem_u32(smraw);

    int tid = threadIdx.x;
    int wid = tid >> 5;
    int lid = tid & 31;
    int g = lid >> 2;                 // mma group 0..7
    int t = lid & 3;                  // thread-in-group
    int rowBase = blockIdx.x * 128;
    int rowWarp = (wid >> 1) * 32;    // warp tile: 32 rows x 64 cols
    int colWarp = (wid & 1) * 64;

    // ldmatrix lane address components
    int aRow = lid & 15, aCk = (lid >> 4) & 1;
    int bRow = ((lid >> 4) << 3) | (lid & 7);
    int bCk  = (lid >> 3) & 1;

    float acc[2][8][4];
    #pragma unroll
    for (int rt = 0; rt < 2; rt++)
        #pragma unroll
        for (int ct = 0; ct < 8; ct++)
            #pragma unroll
            for (int q = 0; q < 4; q++) acc[rt][ct][q] = 0.0f;

    auto load_chunk = [&](int c, int st) {
        const uint32_t* Ah = (c < 4) ? A0h : A1h;
        const uint32_t* Al = (c < 4) ? A0l : A1l;
        int ko = (c & 3) * 16;        // uint32 offset in 64-word row
        int kb = c * 16;              // uint32 offset in 128-word B row
        uint32_t sA = sbase + st * STAGE;
        #pragma unroll
        for (int j = 0; j < 2; j++) {
            int idx = tid + j * 256;
            int r = idx >> 2, ck = idx & 3;
            uint32_t woff = (uint32_t)(r * 64 + ck * 16);
            uint32_t sw = SW64(woff);
            int gr = rowBase + r;
            int sz = (gr < n) ? 16 : 0;
            int grc = (gr < n) ? gr : 0;
            cpasync16(sA + sw,         Ah + (size_t)grc * 64 + ko + ck * 4, sz);
            cpasync16(sA + 8192 + sw,  Al + (size_t)grc * 64 + ko + ck * 4, sz);
            cpasync16(sA + 16384 + sw, Bh + r * 128 + kb + ck * 4, 16);
            cpasync16(sA + 24576 + sw, Bl + r * 128 + kb + ck * 4, 16);
        }
        cp_commit();
    };

    load_chunk(0, 0);

    for (int c = 0; c < 8; c++) {
        if (c < 7) { load_chunk(c + 1, (c + 1) & 1); cp_wait1(); }
        else       { cp_wait0(); }
        __syncthreads();

        uint32_t sA = sbase + (c & 1) * STAGE;

        #pragma unroll
        for (int kk2 = 0; kk2 < 2; kk2++) {
            uint32_t ah[2][4], al[2][4];
            #pragma unroll
            for (int rt = 0; rt < 2; rt++) {
                uint32_t woff = (uint32_t)((rowWarp + rt * 16 + aRow) * 64
                                           + kk2 * 32 + aCk * 16);
                uint32_t ad = sA + SW64(woff);
                ldmx4(ah[rt], ad);
                ldmx4(al[rt], ad + 8192);
            }
            #pragma unroll
            for (int p = 0; p < 4; p++) {
                uint32_t woff = (uint32_t)((colWarp + p * 16 + bRow) * 64
                                           + kk2 * 32 + bCk * 16);
                uint32_t bd = sA + 16384 + SW64(woff);
                uint32_t bh[4], bl[4];
                ldmx4(bh, bd);
                ldmx4(bl, bd + 8192);
                #pragma unroll
                for (int rt = 0; rt < 2; rt++) {
                    mma_bf16(acc[rt][2 * p],     ah[rt], bh[0], bh[1]);
                    mma_bf16(acc[rt][2 * p],     ah[rt], bl[0], bl[1]);
                    mma_bf16(acc[rt][2 * p],     al[rt], bh[0], bh[1]);
                    mma_bf16(acc[rt][2 * p + 1], ah[rt], bh[2], bh[3]);
                    mma_bf16(acc[rt][2 * p + 1], ah[rt], bl[2], bl[3]);
                    mma_bf16(acc[rt][2 * p + 1], al[rt], bh[2], bh[3]);
                }
            }
        }
        __syncthreads();
    }

    // epilogue: bias (+relu); PAIR_OUT -> hi/lo planes, else fp32
    float bc0[8], bc1[8];
    #pragma unroll
    for (int ct = 0; ct < 8; ct++) {
        int col = colWarp + ct * 8 + 2 * t;
        bc0[ct] = __ldg(&bias[col]);
        bc1[ct] = __ldg(&bias[col + 1]);
    }
    #pragma unroll
    for (int rt = 0; rt < 2; rt++) {
        #pragma unroll
        for (int half = 0; half < 2; half++) {
            int grow = rowBase + rowWarp + rt * 16 + half * 8 + g;
            if (grow >= n) continue;
            #pragma unroll
            for (int ct = 0; ct < 8; ct++) {
                int col = colWarp + ct * 8 + 2 * t;
                float v0 = acc[rt][ct][half * 2 + 0] + bc0[ct];
                float v1 = acc[rt][ct][half * 2 + 1] + bc1[ct];
                if (RELU) { v0 = fmaxf(v0, 0.f); v1 = fmaxf(v1, 0.f); }
                if (PAIR_OUT) {
                    uint2 p = split2(v0, v1);
                    Coh[(size_t)grow * 64 + (col >> 1)] = p.x;
                    Col[(size_t)grow * 64 + (col >> 1)] = p.y;
                } else {
                    float2 o; o.x = v0; o.y = v1;
                    *(float2*)&Cof[(size_t)grow * 128 + col] = o;
                }
            }
        }
    }
}

// ----------------------------------- pooled segment sums (batch sorted)
__global__ void k_pool(const float* __restrict__ h2, const int* __restrict__ batch, int n) {
    const int ROWS = 256;
    int tx = threadIdx.x;           // 128 threads: one per feature column
    int r0 = blockIdx.x * ROWS;
    if (r0 >= n) return;
    int rend = r0 + ROWS; if (rend > n) rend = n;
    float acc = 0.0f;
    int cur = batch[r0];
    int cl = 0;
    for (int r = r0; r < rend; r++) {
        int gg = batch[r];
        if (gg != cur) {
            atomicAdd(&g_gsum[cur * DD + tx], acc);
            if (tx == 0) atomicAdd(&g_gcnt[cur], (float)cl);
            acc = 0.0f; cl = 0; cur = gg;
        }
        acc += h2[r * 128 + tx];
        cl++;
    }
    atomicAdd(&g_gsum[cur * DD + tx], acc);
    if (tx == 0) atomicAdd(&g_gcnt[cur], (float)cl);
}

// ---------------- final output (single block; restores zero-invariants)
__global__ void k_final(float* __restrict__ out) {
    __shared__ float sc[NG];
    int t = threadIdx.x;
    if (t < NG) sc[t] = g_gcnt[t];
    __syncthreads();
    for (int i = t; i < NG * DD; i += 1024) {
        out[i] = g_gsum[i] / fmaxf(sc[i >> 7], 1.0f);
        g_gsum[i] = 0.0f;
    }
    if (t < NG) g_gcnt[t] = 0.0f;
}

// ---------------------------------------------------------------------------
extern "C" void kernel_launch(void* const* d_in, const int* in_sizes, int n_in,
                              void* d_out, int out_size) {
    (void)n_in; (void)out_size;
    const float* x     = (const float*)d_in[0];
    const int*   ei    = (const int*)  d_in[1];
    const int*   batch = (const int*)  d_in[2];
    const float* W1l   = (const float*)d_in[3];
    const float* b1    = (const float*)d_in[4];
    const float* W1r   = (const float*)d_in[5];
    const float* W2l   = (const float*)d_in[6];
    const float* b2    = (const float*)d_in[7];
    const float* W2r   = (const float*)d_in[8];
    float*       out   = (float*)d_out;

    int n = in_sizes[0] / 128;   // nodes
    int e = in_sizes[1] / 2;     // edges
    const int* src = ei;         // edge_index[0]
    const int* dst = ei + e;     // edge_index[1]

    void *pxh, *pxl, *pah, *pal, *ph1h, *ph1l, *ph2;
    void *pw1h, *pw1l, *pw2h, *pw2l;
    cudaGetSymbolAddress(&pxh, g_xh);   cudaGetSymbolAddress(&pxl, g_xl);
    cudaGetSymbolAddress(&pah, g_ah);   cudaGetSymbolAddress(&pal, g_al);
    cudaGetSymbolAddress(&ph1h, g_h1h); cudaGetSymbolAddress(&ph1l, g_h1l);
    cudaGetSymbolAddress(&ph2, g_h2);
    cudaGetSymbolAddress(&pw1h, g_w1h); cudaGetSymbolAddress(&pw1l, g_w1l);
    cudaGetSymbolAddress(&pw2h, g_w2h); cudaGetSymbolAddress(&pw2l, g_w2l);

    const int GEMM_SMEM = 2 * STAGE;   // 65536
    cudaFuncSetAttribute(k_gemm<true, true>,
                         cudaFuncAttributeMaxDynamicSharedMemorySize, GEMM_SMEM);
    cudaFuncSetAttribute(k_gemm<false, false>,
                         cudaFuncAttributeMaxDynamicSharedMemorySize, GEMM_SMEM);

    // CSR build (g_cnt arrives zeroed; k_fill restores the invariant)
    k_count   <<<(e + 255) / 256, 256>>>(dst, e);
    k_scan_all<<<1, 1024>>>(n, e);
    k_fill    <<<(e + 255) / 256, 256>>>(src, dst, e, n);

    // One-time conversions (x and weights -> hi/lo planes)
    int cvtTot = n * 64 + 2 * 128 * 128;
    k_cvtall<<<(cvtTot + 255) / 256, 256>>>((const float2*)x, W1l, W1r, W2l, W2r, n);

    int aggBlocks  = (n * 32 + 255) / 256;
    int gemmBlocks = (n + 127) / 128;

    // Layer 1: agg = mean(x[nbr]); h1 = relu([agg,x]@[W1l;W1r] + b1)
    k_agg_f<<<aggBlocks, 256>>>((const float4*)x, n);
    k_gemm<true, true><<<gemmBlocks, 256, GEMM_SMEM>>>(
        (const uint32_t*)pah, (const uint32_t*)pal,
        (const uint32_t*)pxh, (const uint32_t*)pxl,
        (const uint32_t*)pw1h, (const uint32_t*)pw1l,
        b1, (uint32_t*)ph1h, (uint32_t*)ph1l, nullptr, n);

    // Layer 2: agg = mean(h1[nbr]); h2 = [agg,h1]@[W2l;W2r] + b2
    k_agg_p<<<aggBlocks, 256>>>(n);
    k_gemm<false, false><<<gemmBlocks, 256, GEMM_SMEM>>>(
        (const uint32_t*)pah, (const uint32_t*)pal,
        (const uint32_t*)ph1h, (const uint32_t*)ph1l,
        (const uint32_t*)pw2h, (const uint32_t*)pw2l,
        b2, nullptr, nullptr, (float*)ph2, n);

    // Global mean pool (g_gsum/g_gcnt arrive zeroed; k_final restores)
    k_pool <<<(n + 255) / 256, 128>>>((const float*)ph2, batch, n);
    k_final<<<1, 1024>>>(out);
}